// round 7
// baseline (speedup 1.0000x reference)
#include <cuda_runtime.h>
#include <math.h>

#define NQ 20
#define NSTATE (1u << NQ)
#define NMASK (NSTATE - 1u)
#define NBATCH 4

// Ping-pong scratch state buffers (2 x 32 MB) — device globals.
__device__ __align__(16) float2 g_bufA[(size_t)NBATCH << NQ];
__device__ __align__(16) float2 g_bufB[(size_t)NBATCH << NQ];

__device__ __forceinline__ float2 cmulf(float2 a, float2 b) {
    return make_float2(fmaf(a.x, b.x, -a.y * b.y), fmaf(a.x, b.y, a.y * b.x));
}

// XOR swizzle (bijection on [0,4096)) for conflict-reduced smem access
__device__ __forceinline__ unsigned swz(unsigned t) {
    return (t ^ ((t >> 4) & 15u)) & 4095u;
}

template<int K>
__device__ __forceinline__ void h_stage(float2* v) {
    const float r2 = 0.7071067811865476f;
#pragma unroll
    for (int p = 0; p < 8; ++p) {
        int i0 = ((p >> K) << (K + 1)) | (p & ((1 << K) - 1));
        int i1 = i0 | (1 << K);
        float2 a = v[i0], b = v[i1];
        v[i0] = make_float2((a.x + b.x) * r2, (a.y + b.y) * r2);
        v[i1] = make_float2((a.x - b.x) * r2, (a.y - b.y) * r2);
    }
}

template<int K>
__device__ __forceinline__ void rx_stage(float2* v, float c, float s) {
    // RX: [[c, -i s],[-i s, c]]
#pragma unroll
    for (int p = 0; p < 8; ++p) {
        int i0 = ((p >> K) << (K + 1)) | (p & ((1 << K) - 1));
        int i1 = i0 | (1 << K);
        float2 a = v[i0], b = v[i1];
        v[i0] = make_float2(fmaf(c, a.x, s * b.y), fmaf(c, a.y, -s * b.x));
        v[i1] = make_float2(fmaf(c, b.x, s * a.y), fmaf(c, b.y, -s * a.x));
    }
}

__device__ __forceinline__ void h4(float2* v) {
    h_stage<0>(v); h_stage<1>(v); h_stage<2>(v); h_stage<3>(v);
}

// RX on 4 consecutive global bits b0..b0+3 (qubit = 19 - bit).
__device__ __forceinline__ void rx4(float2* v, const float* __restrict__ th, int b0) {
    float c0, s0, c1, s1, c2, s2, c3, s3;
    sincosf(0.5f * th[19 - (b0 + 0)], &s0, &c0);
    sincosf(0.5f * th[19 - (b0 + 1)], &s1, &c1);
    sincosf(0.5f * th[19 - (b0 + 2)], &s2, &c2);
    sincosf(0.5f * th[19 - (b0 + 3)], &s3, &c3);
    rx_stage<0>(v, c0, s0);
    rx_stage<1>(v, c1, s1);
    rx_stage<2>(v, c2, s2);
    rx_stage<3>(v, c3, s3);
}

// ---------------------------------------------------------------------------
// LOW pass: tile = state bits 0..11. 3 radix-16 register rounds.
// src flag: 0 -> in=A,out=B ; 1 -> in=B,out=A. PLANAR_IN reads re/im, writes A.
// FINAL_OUT: fuse the last CNOT chain as a gray-decode scatter of the REAL
// PART into fout (float32, out_size elements).
// ---------------------------------------------------------------------------
template<bool HGATE, bool PLANAR_IN, bool FINAL_OUT>
__global__ void __launch_bounds__(256) k_low(
    const float* __restrict__ in_re, const float* __restrict__ in_im,
    int src, float* __restrict__ fout, const float* __restrict__ thx)
{
    __shared__ float2 tile[4096];
    const unsigned u = threadIdx.x;
    const unsigned blk = blockIdx.x;
    const size_t boff = (size_t)((blk >> 8) & (NBATCH - 1)) << NQ;
    const unsigned base = (blk & 255u) << 12;   // state bits 12..19

    const float2* __restrict__ in = (src & 1) ? g_bufB : g_bufA;
    float2* __restrict__ out = PLANAR_IN ? g_bufA : ((src & 1) ? g_bufA : g_bufB);

    float2 v[16];

    // Round 0: e = bits 0..3
    {
        const unsigned t0 = u << 4;
        const size_t g0 = boff + ((base + t0) & NMASK);
        if (PLANAR_IN) {
#pragma unroll
            for (int j = 0; j < 16; ++j)
                v[j] = make_float2(in_re[g0 + j], in_im[g0 + j]);
        } else {
#pragma unroll
            for (int j = 0; j < 16; ++j)
                v[j] = in[g0 + j];
        }
        if (HGATE) h4(v); else rx4(v, thx, 0);
#pragma unroll
        for (int e = 0; e < 16; ++e) tile[swz(t0 | e)] = v[e];
    }
    __syncthreads();

    // Round 1: e = bits 4..7
    {
        const unsigned tb = ((u >> 4) << 8) | (u & 15u);
#pragma unroll
        for (int e = 0; e < 16; ++e) v[e] = tile[swz(tb | (e << 4))];
        if (HGATE) h4(v); else rx4(v, thx, 4);
#pragma unroll
        for (int e = 0; e < 16; ++e) tile[swz(tb | (e << 4))] = v[e];
    }
    __syncthreads();

    // Round 2: e = bits 8..11
    {
#pragma unroll
        for (int e = 0; e < 16; ++e) v[e] = tile[swz((e << 8) | u)];
        if (HGATE) h4(v); else rx4(v, thx, 8);
        if (FINAL_OUT) {
            // result[i] = state[i ^ (i>>1)] (CNOT chain), emit REAL part only.
            // out[gray_decode(s)] = Re(state[s])
#pragma unroll
            for (int e = 0; e < 16; ++e) {
                unsigned s = base | ((unsigned)e << 8) | u;
                unsigned d = s;
                d ^= d >> 1; d ^= d >> 2; d ^= d >> 4; d ^= d >> 8; d ^= d >> 16;
                fout[boff + (d & NMASK)] = v[e].x;
            }
        } else {
#pragma unroll
            for (int e = 0; e < 16; ++e)
                out[boff + ((base + ((unsigned)e << 8) + u) & NMASK)] = v[e];
        }
    }
}

// ---------------------------------------------------------------------------
// HIGH pass (first): H on bits 12..19, RZ(layer0, all), RX(layer0, 12..19).
// ---------------------------------------------------------------------------
__global__ void __launch_bounds__(256) k_high_first(
    int src, const float* __restrict__ thz, const float* __restrict__ thx)
{
    __shared__ float2 tile[4096];
    __shared__ float2 zf[16];            // cis(phase) over bits 16..19
    const unsigned u = threadIdx.x;
    const unsigned blk = blockIdx.x;
    const size_t boff = (size_t)((blk >> 8) & (NBATCH - 1)) << NQ;
    const unsigned base4 = (blk & 255u) << 4;   // state bits 4..11

    const float2* __restrict__ in = (src & 1) ? g_bufB : g_bufA;
    float2* __restrict__ out = (src & 1) ? g_bufA : g_bufB;

    if (u < 16) {
        float ph = 0.f;
#pragma unroll
        for (int k = 0; k < 4; ++k) {
            float t = 0.5f * thz[19 - (16 + k)];
            ph += ((u >> k) & 1u) ? t : -t;
        }
        float sp, cp; sincosf(ph, &sp, &cp);
        zf[u] = make_float2(cp, sp);
    }

    float2 v[16];
    const unsigned tb0 = ((u >> 4) << 8) | (u & 15u);

    // Round 0: e ~ bits 12..15 : H
    {
        const unsigned gfix = base4 | (u & 15u) | ((u >> 4) << 16);
#pragma unroll
        for (int e = 0; e < 16; ++e)
            v[e] = in[boff + ((gfix | ((unsigned)e << 12)) & NMASK)];
        h4(v);
#pragma unroll
        for (int e = 0; e < 16; ++e) tile[swz(tb0 | (e << 4))] = v[e];
    }
    __syncthreads();

    // Round 1: e ~ bits 16..19 : H, RZ(all), RX(16..19)
    {
#pragma unroll
        for (int e = 0; e < 16; ++e) v[e] = tile[swz((e << 8) | u)];
        h4(v);
        const unsigned g0 = base4 | (u & 15u) | ((u >> 4) << 12);  // bits 0..15
        float ph = 0.f;
#pragma unroll
        for (int b = 0; b < 16; ++b) {
            float t = 0.5f * thz[19 - b];
            ph += ((g0 >> b) & 1u) ? t : -t;
        }
        float sp, cp; sincosf(ph, &sp, &cp);
        float2 fz = make_float2(cp, sp);
#pragma unroll
        for (int e = 0; e < 16; ++e) v[e] = cmulf(v[e], cmulf(fz, zf[e]));
        rx4(v, thx, 16);
#pragma unroll
        for (int e = 0; e < 16; ++e) tile[swz((e << 8) | u)] = v[e];
    }
    __syncthreads();

    // Round 2: e ~ bits 12..15 : RX(12..15), store
    {
#pragma unroll
        for (int e = 0; e < 16; ++e) v[e] = tile[swz(tb0 | (e << 4))];
        rx4(v, thx, 12);
        const unsigned gfix = base4 | (u & 15u) | ((u >> 4) << 16);
#pragma unroll
        for (int e = 0; e < 16; ++e)
            out[boff + ((gfix | ((unsigned)e << 12)) & NMASK)] = v[e];
    }
}

// ---------------------------------------------------------------------------
// HIGH pass (mid): gray-gather (fused CNOT chain), RZ(layer, all), RX(layer, 12..19).
// ---------------------------------------------------------------------------
__global__ void __launch_bounds__(256) k_high_mid(
    int src, const float* __restrict__ thz, const float* __restrict__ thx)
{
    __shared__ float2 tile[4096];
    __shared__ float2 zf[16];            // cis(phase) over bits 12..15
    const unsigned u = threadIdx.x;
    const unsigned blk = blockIdx.x;
    const size_t boff = (size_t)((blk >> 8) & (NBATCH - 1)) << NQ;
    const unsigned base4 = (blk & 255u) << 4;   // state bits 4..11

    const float2* __restrict__ in = (src & 1) ? g_bufB : g_bufA;
    float2* __restrict__ out = (src & 1) ? g_bufA : g_bufB;

    if (u < 16) {
        float ph = 0.f;
#pragma unroll
        for (int k = 0; k < 4; ++k) {
            float t = 0.5f * thz[19 - (12 + k)];
            ph += ((u >> k) & 1u) ? t : -t;
        }
        float sp, cp; sincosf(ph, &sp, &cp);
        zf[u] = make_float2(cp, sp);
    }
    __syncthreads();

    float2 v[16];

    // Round 0: e ~ bits 12..15 : gray gather + RZ + RX(12..15)
    {
        const unsigned gfix = base4 | (u & 15u) | ((u >> 4) << 16);
        float ph = 0.f;
#pragma unroll
        for (int b = 0; b < 12; ++b) {
            float t = 0.5f * thz[19 - b];
            ph += ((gfix >> b) & 1u) ? t : -t;
        }
#pragma unroll
        for (int b = 16; b < 20; ++b) {
            float t = 0.5f * thz[19 - b];
            ph += ((gfix >> b) & 1u) ? t : -t;
        }
        float sp, cp; sincosf(ph, &sp, &cp);
        float2 fz = make_float2(cp, sp);

#pragma unroll
        for (int e = 0; e < 16; ++e) {
            unsigned g = gfix | ((unsigned)e << 12);
            unsigned a = (g ^ (g >> 1)) & NMASK;   // CNOT chain = binary->gray
            float2 val = in[boff + a];
            v[e] = cmulf(val, cmulf(fz, zf[e]));
        }
        rx4(v, thx, 12);
        const unsigned tb = ((u >> 4) << 8) | (u & 15u);
#pragma unroll
        for (int e = 0; e < 16; ++e) tile[swz(tb | (e << 4))] = v[e];
    }
    __syncthreads();

    // Round 1: e ~ bits 16..19 : RX(16..19), store
    {
#pragma unroll
        for (int e = 0; e < 16; ++e) v[e] = tile[swz((e << 8) | u)];
        rx4(v, thx, 16);
#pragma unroll
        for (int e = 0; e < 16; ++e) {
            unsigned g = base4 | (u & 15u) | ((u >> 4) << 12) | ((unsigned)e << 16);
            out[boff + (g & NMASK)] = v[e];
        }
    }
}

extern "C" void kernel_launch(void* const* d_in, const int* in_sizes, int n_in,
                              void* d_out, int out_size) {
    // Bind by size class: big inputs in order = psi0_real, psi0_imag;
    // small inputs in order = thetas_x, thetas_z.
    const float *re = nullptr, *im = nullptr, *thx = nullptr, *thz = nullptr;
    for (int i = 0; i < n_in; ++i) {
        if (in_sizes[i] > 1024) {
            if (!re) re = (const float*)d_in[i];
            else if (!im) im = (const float*)d_in[i];
        } else {
            if (!thx) thx = (const float*)d_in[i];
            else if (!thz) thz = (const float*)d_in[i];
        }
    }
    if (!re || !im || !thx || !thz) return;

    const dim3 gr(NBATCH * 256);
    const int th = 256;

    // P1: H bits 0..11, planar -> A
    k_low<true, true, false><<<gr, th>>>(re, im, 1, nullptr, nullptr);
    // P2: H bits 12..19 + RZ0 + RX0(high)   A -> B
    k_high_first<<<gr, th>>>(0, thz + 0, thx + 0);
    // P3: RX0(low)                          B -> A
    k_low<false, false, false><<<gr, th>>>(nullptr, nullptr, 1, nullptr, thx + 0);
    // P4: gray0 + RZ1 + RX1(high)           A -> B
    k_high_mid<<<gr, th>>>(0, thz + 20, thx + 20);
    // P5: RX1(low)                          B -> A
    k_low<false, false, false><<<gr, th>>>(nullptr, nullptr, 1, nullptr, thx + 20);
    // P6: gray1 + RZ2 + RX2(high)           A -> B
    k_high_mid<<<gr, th>>>(0, thz + 40, thx + 40);
    // P7: RX2(low)                          B -> A
    k_low<false, false, false><<<gr, th>>>(nullptr, nullptr, 1, nullptr, thx + 40);
    // P8: gray2 + RZ3 + RX3(high)           A -> B
    k_high_mid<<<gr, th>>>(0, thz + 60, thx + 60);
    // P9: RX3(low) + gray3 scatter of REAL PART -> d_out (float32, out_size elems)
    k_low<false, false, true><<<gr, th>>>(nullptr, nullptr, 1, (float*)d_out, thx + 60);
}

// round 8
// speedup vs baseline: 1.1156x; 1.1156x over previous
#include <cuda_runtime.h>
#include <math.h>

#define NQ 20
#define NSTATE (1u << NQ)
#define NPAIR 2   // batch pairs (B=4 -> 2 pairs packed into f32x2 lanes)
typedef unsigned long long ull;

// Scratch state, batch-pair packed: element = ulonglong2{ R=(re_b0,re_b1), I=(im_b0,im_b1) }
__device__ __align__(16) ulonglong2 g_bufA[(size_t)NPAIR << NQ];
__device__ __align__(16) ulonglong2 g_bufB[(size_t)NPAIR << NQ];
// Precomputed per (layer, state-bit): RX (cos(t/2), sin(t/2)) and RZ half-angles
__device__ float2 g_cs[4 * 32];
__device__ float  g_hz[4 * 32];

struct P2 { ull R, I; };

__device__ __forceinline__ ull pk2(float lo, float hi) {
    ull r; asm("mov.b64 %0,{%1,%2};" : "=l"(r) : "f"(lo), "f"(hi)); return r;
}
__device__ __forceinline__ void upk2(ull v, float& lo, float& hi) {
    asm("mov.b64 {%0,%1},%2;" : "=f"(lo), "=f"(hi) : "l"(v));
}
__device__ __forceinline__ ull dup2(float x) { return pk2(x, x); }
__device__ __forceinline__ ull f2mul(ull a, ull b) {
    ull r; asm("mul.rn.f32x2 %0,%1,%2;" : "=l"(r) : "l"(a), "l"(b)); return r;
}
__device__ __forceinline__ ull f2fma(ull a, ull b, ull c) {
    ull r; asm("fma.rn.f32x2 %0,%1,%2,%3;" : "=l"(r) : "l"(a), "l"(b), "l"(c)); return r;
}

// RX butterfly: v0' = c v0 - i s v1 ; v1' = -i s v0 + c v1
__device__ __forceinline__ void rx_bfly(P2& a, P2& b, ull cc, ull ss, ull ns) {
    ull r0 = f2fma(a.R, cc, f2mul(b.I, ss));
    ull i0 = f2fma(a.I, cc, f2mul(b.R, ns));
    ull r1 = f2fma(b.R, cc, f2mul(a.I, ss));
    ull i1 = f2fma(b.I, cc, f2mul(a.R, ns));
    a.R = r0; a.I = i0; b.R = r1; b.I = i1;
}
__device__ __forceinline__ void h_bfly(P2& a, P2& b, ull rr, ull nr) {
    ull r0 = f2fma(a.R, rr, f2mul(b.R, rr));
    ull i0 = f2fma(a.I, rr, f2mul(b.I, rr));
    ull r1 = f2fma(a.R, rr, f2mul(b.R, nr));
    ull i1 = f2fma(a.I, rr, f2mul(b.I, nr));
    a.R = r0; a.I = i0; b.R = r1; b.I = i1;
}
// v *= (fr + i fi)
__device__ __forceinline__ void ph_apply(P2& a, ull cc, ull ss, ull ns) {
    ull r = f2fma(a.R, cc, f2mul(a.I, ns));
    ull i = f2fma(a.I, cc, f2mul(a.R, ss));
    a.R = r; a.I = i;
}

template<int K> __device__ __forceinline__ void rx_stage8(P2* v, float2 cs) {
    ull cc = dup2(cs.x), ss = dup2(cs.y), ns = dup2(-cs.y);
#pragma unroll
    for (int p = 0; p < 4; ++p) {
        int i0 = ((p >> K) << (K + 1)) | (p & ((1 << K) - 1));
        rx_bfly(v[i0], v[i0 | (1 << K)], cc, ss, ns);
    }
}
template<int K> __device__ __forceinline__ void h_stage8(P2* v) {
    const float r2 = 0.7071067811865476f;
    ull rr = dup2(r2), nr = dup2(-r2);
#pragma unroll
    for (int p = 0; p < 4; ++p) {
        int i0 = ((p >> K) << (K + 1)) | (p & ((1 << K) - 1));
        h_bfly(v[i0], v[i0 | (1 << K)], rr, nr);
    }
}
__device__ __forceinline__ void h3(P2* v) { h_stage8<0>(v); h_stage8<1>(v); h_stage8<2>(v); }
__device__ __forceinline__ void rx3(P2* v, int l, int b0) {
    rx_stage8<0>(v, g_cs[l * 32 + b0 + 0]);
    rx_stage8<1>(v, g_cs[l * 32 + b0 + 1]);
    rx_stage8<2>(v, g_cs[l * 32 + b0 + 2]);
}

// smem swizzle: distinct (sw&7) within each 8-lane phase for all access patterns
__device__ __forceinline__ unsigned sw(unsigned t) { return t ^ ((t >> 3) & 7u); }

// Setup: per (layer, bit) RX coefs + RZ half angles (theta index = l*20 + (19-bit))
__global__ void k_setup(const float* __restrict__ thx, const float* __restrict__ thz) {
    int i = threadIdx.x;
    if (i < 80) {
        int l = i / 20, q = i % 20, bit = 19 - q;
        float s, c; sincosf(0.5f * thx[i], &s, &c);
        g_cs[l * 32 + bit] = make_float2(c, s);
        g_hz[l * 32 + bit] = 0.5f * thz[i];
    }
}

// ---------------------------------------------------------------------------
// LOW pass: tile = state bits 0..10 (2048 packed elements), 256 thr x 8 elems.
// Rounds: bits 0..2 | 3..5 | 6..8 | 9..10. HG: Hadamards; else RX layer l.
// FO: final gray-decode scatter of real parts into fout.
// src: 1 -> in=B,out=A ; 0 -> in=A,out=B. (PL reads planar, writes A via src=1.)
// ---------------------------------------------------------------------------
template<bool HG, bool PL, bool FO>
__global__ void __launch_bounds__(256) k_low(
    const float* __restrict__ re, const float* __restrict__ im,
    int src, float* __restrict__ fout, int l)
{
    __shared__ ulonglong2 ts[2048];
    const unsigned u = threadIdx.x, blk = blockIdx.x;
    const unsigned pair = blk >> 9, tile = blk & 511u;
    const unsigned base = tile << 11;                 // state bits 11..19
    const size_t poff = (size_t)pair << NQ;

    const ulonglong2* __restrict__ in = (src & 1) ? g_bufB : g_bufA;
    ulonglong2* __restrict__ out = (src & 1) ? g_bufA : g_bufB;

    P2 v[8];
    // R0: e = bits 0..2
    {
        const unsigned t0 = u << 3;
        if (PL) {
            size_t b0 = ((size_t)(2 * pair) << NQ) + base + t0;
            const float4* r0p = (const float4*)(re + b0);
            const float4* r1p = (const float4*)(re + b0 + NSTATE);
            const float4* i0p = (const float4*)(im + b0);
            const float4* i1p = (const float4*)(im + b0 + NSTATE);
#pragma unroll
            for (int j = 0; j < 2; ++j) {
                float4 ra = r0p[j], rb = r1p[j], ia = i0p[j], ib = i1p[j];
                v[4 * j + 0].R = pk2(ra.x, rb.x); v[4 * j + 0].I = pk2(ia.x, ib.x);
                v[4 * j + 1].R = pk2(ra.y, rb.y); v[4 * j + 1].I = pk2(ia.y, ib.y);
                v[4 * j + 2].R = pk2(ra.z, rb.z); v[4 * j + 2].I = pk2(ia.z, ib.z);
                v[4 * j + 3].R = pk2(ra.w, rb.w); v[4 * j + 3].I = pk2(ia.w, ib.w);
            }
        } else {
#pragma unroll
            for (int e = 0; e < 8; ++e) {
                ulonglong2 w = in[poff + base + t0 + e]; v[e].R = w.x; v[e].I = w.y;
            }
        }
        if (HG) h3(v); else rx3(v, l, 0);
#pragma unroll
        for (int e = 0; e < 8; ++e) ts[sw(t0 | e)] = make_ulonglong2(v[e].R, v[e].I);
    }
    __syncthreads();
    // R1: e = bits 3..5
    {
        const unsigned tb = ((u >> 3) << 6) | (u & 7u);
#pragma unroll
        for (int e = 0; e < 8; ++e) { ulonglong2 w = ts[sw(tb | (e << 3))]; v[e].R = w.x; v[e].I = w.y; }
        if (HG) h3(v); else rx3(v, l, 3);
#pragma unroll
        for (int e = 0; e < 8; ++e) ts[sw(tb | (e << 3))] = make_ulonglong2(v[e].R, v[e].I);
    }
    __syncthreads();
    // R2: e = bits 6..8
    {
        const unsigned tb = ((u >> 6) << 9) | (u & 63u);
#pragma unroll
        for (int e = 0; e < 8; ++e) { ulonglong2 w = ts[sw(tb | (e << 6))]; v[e].R = w.x; v[e].I = w.y; }
        if (HG) h3(v); else rx3(v, l, 6);
#pragma unroll
        for (int e = 0; e < 8; ++e) ts[sw(tb | (e << 6))] = make_ulonglong2(v[e].R, v[e].I);
    }
    __syncthreads();
    // R3: e = bits 8..10 (bit 8 already gated in R2); gates on bits 9,10
    {
#pragma unroll
        for (int e = 0; e < 8; ++e) { ulonglong2 w = ts[sw((e << 8) | u)]; v[e].R = w.x; v[e].I = w.y; }
        if (HG) { h_stage8<1>(v); h_stage8<2>(v); }
        else { rx_stage8<1>(v, g_cs[l * 32 + 9]); rx_stage8<2>(v, g_cs[l * 32 + 10]); }
        if (FO) {
            // out[i] = Re(state[i ^ (i>>1)])  <=>  fout[graydecode(s)] = Re(state[s])
#pragma unroll
            for (int e = 0; e < 8; ++e) {
                unsigned s = base | ((unsigned)e << 8) | u;
                unsigned d = s; d ^= d >> 1; d ^= d >> 2; d ^= d >> 4; d ^= d >> 8; d ^= d >> 16;
                float lo, hi; upk2(v[e].R, lo, hi);
                fout[((size_t)(2 * pair) << NQ) + d] = lo;
                fout[((size_t)(2 * pair + 1) << NQ) + d] = hi;
            }
        } else {
#pragma unroll
            for (int e = 0; e < 8; ++e)
                out[poff + base + ((unsigned)e << 8) + u] = make_ulonglong2(v[e].R, v[e].I);
        }
    }
}

// ---------------------------------------------------------------------------
// HIGH first (layer 0): per round r: H(bits), RZ-phase slice, RX(bits).
// Tile local bits {0,1} U {11..19}; block fixes bits 2..10.
// Valid ordering: per-qubit H->RZ->RX preserved; cross-qubit gates commute.
// ---------------------------------------------------------------------------
__global__ void __launch_bounds__(256) k_highf(int src, int l)
{
    __shared__ ulonglong2 ts[2048];
    __shared__ float2 zfs[3][8];
    __shared__ float hz_s[20];
    const unsigned u = threadIdx.x, blk = blockIdx.x;
    const unsigned pair = blk >> 9, tile = blk & 511u;
    const unsigned mid = tile << 2;                  // state bits 2..10
    const size_t poff = (size_t)pair << NQ;

    const ulonglong2* __restrict__ in = (src & 1) ? g_bufB : g_bufA;
    ulonglong2* __restrict__ out = (src & 1) ? g_bufA : g_bufB;

    if (u < 20) hz_s[u] = g_hz[l * 32 + u];
    if (u < 24) {
        int tb = u >> 3, e = u & 7;
        float ph = 0.f;
#pragma unroll
        for (int k = 0; k < 3; ++k) {
            float t = g_hz[l * 32 + 11 + tb * 3 + k];
            ph += ((e >> k) & 1) ? t : -t;
        }
        float sp, cp; sincosf(ph, &sp, &cp);
        zfs[tb][e & 7] = make_float2(cp, sp);
    }
    __syncthreads();

    P2 v[8];
    const unsigned low2 = u & 3u, hi6 = u >> 2;
    const unsigned gfix = (hi6 << 14) | mid | low2;

    // R0: e = state 11..13 : H + phase(bits 0..13) + RX
    {
#pragma unroll
        for (int e = 0; e < 8; ++e) {
            ulonglong2 w = in[poff + (gfix | ((unsigned)e << 11))]; v[e].R = w.x; v[e].I = w.y;
        }
        h3(v);
        float ph = 0.f;
#pragma unroll
        for (int b = 0; b < 11; ++b) ph += ((gfix >> b) & 1u) ? hz_s[b] : -hz_s[b];
        float sp, cp; sincosf(ph, &sp, &cp);
#pragma unroll
        for (int e = 0; e < 8; ++e) {
            float2 z = zfs[0][e];
            float fr = fmaf(cp, z.x, -sp * z.y);
            float fi = fmaf(cp, z.y, sp * z.x);
            ph_apply(v[e], dup2(fr), dup2(fi), dup2(-fi));
        }
        rx3(v, l, 11);
        const unsigned tb = (hi6 << 5) | low2;
#pragma unroll
        for (int e = 0; e < 8; ++e) ts[sw(tb | (e << 2))] = make_ulonglong2(v[e].R, v[e].I);
    }
    __syncthreads();
    // R1: e = state 14..16 : H + phase + RX
    {
        const unsigned tb = ((u >> 5) << 8) | (u & 31u);
#pragma unroll
        for (int e = 0; e < 8; ++e) { ulonglong2 w = ts[sw(tb | (e << 5))]; v[e].R = w.x; v[e].I = w.y; }
        h3(v);
#pragma unroll
        for (int e = 0; e < 8; ++e) {
            float2 z = zfs[1][e];
            ph_apply(v[e], dup2(z.x), dup2(z.y), dup2(-z.y));
        }
        rx3(v, l, 14);
#pragma unroll
        for (int e = 0; e < 8; ++e) ts[sw(tb | (e << 5))] = make_ulonglong2(v[e].R, v[e].I);
    }
    __syncthreads();
    // R2: e = state 17..19 : H + phase + RX, store linear
    {
#pragma unroll
        for (int e = 0; e < 8; ++e) { ulonglong2 w = ts[sw((e << 8) | u)]; v[e].R = w.x; v[e].I = w.y; }
        h3(v);
#pragma unroll
        for (int e = 0; e < 8; ++e) {
            float2 z = zfs[2][e];
            ph_apply(v[e], dup2(z.x), dup2(z.y), dup2(-z.y));
        }
        rx3(v, l, 17);
        const unsigned gl = mid | (u & 3u) | (((u >> 2) & 63u) << 11);
#pragma unroll
        for (int e = 0; e < 8; ++e)
            out[poff + (gl | ((unsigned)e << 17))] = make_ulonglong2(v[e].R, v[e].I);
    }
}

// ---------------------------------------------------------------------------
// HIGH mid (layers 1..3): gray gather (fused CNOT chain of previous layer),
// RZ(layer, all 20 bits), RX(layer, bits 11..19).
// ---------------------------------------------------------------------------
__global__ void __launch_bounds__(256) k_highm(int src, int l)
{
    __shared__ ulonglong2 ts[2048];
    __shared__ float2 zf0[8];
    __shared__ float hz_s[20];
    const unsigned u = threadIdx.x, blk = blockIdx.x;
    const unsigned pair = blk >> 9, tile = blk & 511u;
    const unsigned mid = tile << 2;                  // state bits 2..10
    const size_t poff = (size_t)pair << NQ;

    const ulonglong2* __restrict__ in = (src & 1) ? g_bufB : g_bufA;
    ulonglong2* __restrict__ out = (src & 1) ? g_bufA : g_bufB;

    if (u < 20) hz_s[u] = g_hz[l * 32 + u];
    if (u < 8) {
        float ph = 0.f;
#pragma unroll
        for (int k = 0; k < 3; ++k) {
            float t = g_hz[l * 32 + 11 + k];
            ph += ((u >> k) & 1u) ? t : -t;
        }
        float sp, cp; sincosf(ph, &sp, &cp);
        zf0[u] = make_float2(cp, sp);
    }
    __syncthreads();

    P2 v[8];
    const unsigned low2 = u & 3u, hi6 = u >> 2;
    const unsigned gfix = (hi6 << 14) | mid | low2;

    // R0: gray gather + full RZ phase + RX(11..13)
    {
        float ph = 0.f;
#pragma unroll
        for (int b = 0; b < 11; ++b) ph += ((gfix >> b) & 1u) ? hz_s[b] : -hz_s[b];
#pragma unroll
        for (int b = 14; b < 20; ++b) ph += ((gfix >> b) & 1u) ? hz_s[b] : -hz_s[b];
        float sp, cp; sincosf(ph, &sp, &cp);
#pragma unroll
        for (int e = 0; e < 8; ++e) {
            unsigned g = gfix | ((unsigned)e << 11);
            unsigned a = g ^ (g >> 1);               // CNOT chain = binary->gray
            ulonglong2 w = in[poff + a]; v[e].R = w.x; v[e].I = w.y;
            float2 z = zf0[e];
            float fr = fmaf(cp, z.x, -sp * z.y);
            float fi = fmaf(cp, z.y, sp * z.x);
            ph_apply(v[e], dup2(fr), dup2(fi), dup2(-fi));
        }
        rx3(v, l, 11);
        const unsigned tb = (hi6 << 5) | low2;
#pragma unroll
        for (int e = 0; e < 8; ++e) ts[sw(tb | (e << 2))] = make_ulonglong2(v[e].R, v[e].I);
    }
    __syncthreads();
    // R1: RX(14..16)
    {
        const unsigned tb = ((u >> 5) << 8) | (u & 31u);
#pragma unroll
        for (int e = 0; e < 8; ++e) { ulonglong2 w = ts[sw(tb | (e << 5))]; v[e].R = w.x; v[e].I = w.y; }
        rx3(v, l, 14);
#pragma unroll
        for (int e = 0; e < 8; ++e) ts[sw(tb | (e << 5))] = make_ulonglong2(v[e].R, v[e].I);
    }
    __syncthreads();
    // R2: RX(17..19), store linear
    {
#pragma unroll
        for (int e = 0; e < 8; ++e) { ulonglong2 w = ts[sw((e << 8) | u)]; v[e].R = w.x; v[e].I = w.y; }
        rx3(v, l, 17);
        const unsigned gl = mid | (u & 3u) | (((u >> 2) & 63u) << 11);
#pragma unroll
        for (int e = 0; e < 8; ++e)
            out[poff + (gl | ((unsigned)e << 17))] = make_ulonglong2(v[e].R, v[e].I);
    }
}

extern "C" void kernel_launch(void* const* d_in, const int* in_sizes, int n_in,
                              void* d_out, int out_size) {
    const float *re = nullptr, *im = nullptr, *thx = nullptr, *thz = nullptr;
    for (int i = 0; i < n_in; ++i) {
        if (in_sizes[i] > 1024) {
            if (!re) re = (const float*)d_in[i];
            else if (!im) im = (const float*)d_in[i];
        } else {
            if (!thx) thx = (const float*)d_in[i];
            else if (!thz) thz = (const float*)d_in[i];
        }
    }
    if (!re || !im || !thx || !thz) return;

    const dim3 gr(NPAIR * 512);
    const int th = 256;

    k_setup<<<1, 128>>>(thx, thz);
    // P1: H bits 0..10, planar -> A
    k_low<true, true, false><<<gr, th>>>(re, im, 1, nullptr, 0);
    // P2: H bits 11..19 + RZ0 + RX0(high)    A -> B
    k_highf<<<gr, th>>>(0, 0);
    // P3: RX0 bits 0..10                     B -> A
    k_low<false, false, false><<<gr, th>>>(nullptr, nullptr, 1, nullptr, 0);
    // P4: gray0 + RZ1 + RX1(high)            A -> B
    k_highm<<<gr, th>>>(0, 1);
    // P5: RX1(low)                           B -> A
    k_low<false, false, false><<<gr, th>>>(nullptr, nullptr, 1, nullptr, 1);
    // P6: gray1 + RZ2 + RX2(high)            A -> B
    k_highm<<<gr, th>>>(0, 2);
    // P7: RX2(low)                           B -> A
    k_low<false, false, false><<<gr, th>>>(nullptr, nullptr, 1, nullptr, 2);
    // P8: gray2 + RZ3 + RX3(high)            A -> B
    k_highm<<<gr, th>>>(0, 3);
    // P9: RX3(low) + gray3 scatter of REAL parts -> d_out
    k_low<false, false, true><<<gr, th>>>(nullptr, nullptr, 1, (float*)d_out, 3);
}